// round 14
// baseline (speedup 1.0000x reference)
#include <cuda_runtime.h>
#include <stdint.h>

#define NB 2
#define NH 4
#define NN 8192
#define NK 32
#define NROWS 8
#define PERM_ELEMS (NB * NN * NH * NK * NK)   // 67,108,864
#define IDX_BASE   PERM_ELEMS

typedef unsigned long long u64;
typedef unsigned int u32;

// Scratch (device globals -> no allocation)
__device__ u64 g_keys[NROWS * NN];
__device__ int g_inv [NROWS * NN];

__device__ __forceinline__ u32 f2u(float f) {
    u32 b = __float_as_uint(f);
    return (b & 0x80000000u) ? ~b : (b | 0x80000000u);
}
__device__ __forceinline__ void cswap(u64& a, u64& b, bool asc) {
    if ((a > b) == asc) { u64 t = a; a = b; b = t; }
}
__device__ __forceinline__ void cluster_sync() {
    asm volatile("barrier.cluster.arrive.aligned;" ::: "memory");
    asm volatile("barrier.cluster.wait.aligned;" ::: "memory");
}
__device__ __forceinline__ u32 smem_u32(const void* p) {
    u32 a;
    asm("{ .reg .u64 t; cvta.to.shared.u64 t, %1; cvt.u32.u64 %0, t; }"
        : "=r"(a) : "l"(p));
    return a;
}
__device__ __forceinline__ u32 mapa_rank(u32 local, u32 rank) {
    u32 r;
    asm("mapa.shared::cluster.u32 %0, %1, %2;" : "=r"(r) : "r"(local), "r"(rank));
    return r;
}

// ---- warp-local pieces (validated; 128-elem segments) ----
__device__ __forceinline__ void warp_gen(u64* sh, int seg, int lane,
                                         int jhi, int k) {
    for (int j = jhi; j >= 4; j >>= 1) {
#pragma unroll
        for (int t = lane; t < 64; t += 32) {
            int i = ((t & ~(j - 1)) << 1) | (t & (j - 1));
            int p = i | j;
            bool asc = (((seg + i) & k) == 0);
            u64 a = sh[seg + i], b = sh[seg + p];
            if ((a > b) == asc) { sh[seg + i] = b; sh[seg + p] = a; }
        }
        __syncwarp();
    }
    int eb = seg + (lane << 2);
    bool asc = (((seg + (lane << 2)) & k) == 0);
    u64 e0 = sh[eb], e1 = sh[eb + 1], e2 = sh[eb + 2], e3 = sh[eb + 3];
    cswap(e0, e2, asc); cswap(e1, e3, asc);
    cswap(e0, e1, asc); cswap(e2, e3, asc);
    sh[eb] = e0; sh[eb + 1] = e1; sh[eb + 2] = e2; sh[eb + 3] = e3;
    __syncwarp();
}

__device__ __forceinline__ void warp_finish64(u64* sh, int seg, int lane,
                                              bool asc) {
    int b = seg + lane;
    {
        u64 e0 = sh[b], e1 = sh[b + 32], e2 = sh[b + 64], e3 = sh[b + 96];
        cswap(e0, e2, asc); cswap(e1, e3, asc);    // j=64
        cswap(e0, e1, asc); cswap(e2, e3, asc);    // j=32
        sh[b] = e0; sh[b + 32] = e1; sh[b + 64] = e2; sh[b + 96] = e3;
    }
    __syncwarp();
    for (int j = 16; j >= 4; j >>= 1) {
#pragma unroll
        for (int t = lane; t < 64; t += 32) {
            int i = ((t & ~(j - 1)) << 1) | (t & (j - 1));
            int p = i | j;
            u64 a = sh[seg + i], bb = sh[seg + p];
            if ((a > bb) == asc) { sh[seg + i] = bb; sh[seg + p] = a; }
        }
        __syncwarp();
    }
    int eb = seg + (lane << 2);
    u64 f0 = sh[eb], f1 = sh[eb + 1], f2 = sh[eb + 2], f3 = sh[eb + 3];
    cswap(f0, f2, asc); cswap(f1, f3, asc);
    cswap(f0, f1, asc); cswap(f2, f3, asc);
    sh[eb] = f0; sh[eb + 1] = f1; sh[eb + 2] = f2; sh[eb + 3] = f3;
    __syncwarp();
}

// ---- chunk=1024 register-fused block phases (256 threads) ----
__device__ __forceinline__ void fuse_512_256(u64* sh, int tid, bool asc) {
    u64 e0 = sh[tid], e1 = sh[tid + 256], e2 = sh[tid + 512], e3 = sh[tid + 768];
    cswap(e0, e2, asc); cswap(e1, e3, asc);    // j=512
    cswap(e0, e1, asc); cswap(e2, e3, asc);    // j=256
    sh[tid] = e0; sh[tid + 256] = e1; sh[tid + 512] = e2; sh[tid + 768] = e3;
    __syncthreads();
}
__device__ __forceinline__ void fuse_256_128(u64* sh, int tid, bool asc) {
    int b = ((tid >> 7) << 9) | (tid & 127);
    u64 e0 = sh[b], e1 = sh[b + 128], e2 = sh[b + 256], e3 = sh[b + 384];
    cswap(e0, e2, asc); cswap(e1, e3, asc);    // j=256
    cswap(e0, e1, asc); cswap(e2, e3, asc);    // j=128
    sh[b] = e0; sh[b + 128] = e1; sh[b + 256] = e2; sh[b + 384] = e3;
    __syncthreads();
}
__device__ __forceinline__ void pair128(u64* sh, int tid, bool asc) {
    int b = ((tid >> 7) << 9) | (tid & 127);
    u64 e0 = sh[b], e1 = sh[b + 128], e2 = sh[b + 256], e3 = sh[b + 384];
    cswap(e0, e1, asc); cswap(e2, e3, asc);
    sh[b] = e0; sh[b + 128] = e1; sh[b + 256] = e2; sh[b + 384] = e3;
    __syncthreads();
}
__device__ __forceinline__ void pair128_k256(u64* sh, int tid) {
    int b = ((tid >> 7) << 9) | (tid & 127);
    u64 e0 = sh[b], e1 = sh[b + 128], e2 = sh[b + 256], e3 = sh[b + 384];
    cswap(e0, e1, true); cswap(e2, e3, false);
    sh[b] = e0; sh[b + 128] = e1; sh[b + 256] = e2; sh[b + 384] = e3;
    __syncthreads();
}

__device__ __forceinline__ void exchange(u64* sh, u32 shbase, int partner,
                                         bool keep_min, int tid) {
    cluster_sync();
    u64 peer[4];
    u32 remote = mapa_rank(shbase, (u32)partner);
#pragma unroll
    for (int m = 0; m < 4; m++) {
        u32 addr = remote + (u32)((tid + (m << 8)) << 3);
        asm volatile("ld.shared::cluster.b64 %0, [%1];" : "=l"(peer[m]) : "r"(addr));
    }
    cluster_sync();
#pragma unroll
    for (int m = 0; m < 4; m++) {
        int l = tid + (m << 8);
        u64 mine = sh[l];
        bool take = keep_min ? (peer[m] < mine) : (peer[m] > mine);
        if (take) sh[l] = peer[m];
    }
}

// -------------------------------------------------------------------------
// Full stable argsort of 8 rows x 8192, ONE launch, 64 CTAs. (R13-validated)
// -------------------------------------------------------------------------
__global__ void __launch_bounds__(256) __cluster_dims__(8, 1, 1)
sortCluster8(const float* __restrict__ r) {
    __shared__ u64 sh[1024];
    int tid  = threadIdx.x, lane = tid & 31, warp = tid >> 5;
    int row  = blockIdx.x >> 3;
    int rank = blockIdx.x & 7;
    int base = rank << 10;
    const float* rr = r + row * NN;
    u32 shbase = smem_u32(sh);
    int seg = warp << 7;

    {
        int q = tid << 2;
        float4 f = *reinterpret_cast<const float4*>(rr + base + q);
        u64 e0 = ((u64)f2u(f.x) << 32) | (u32)(base + q);
        u64 e1 = ((u64)f2u(f.y) << 32) | (u32)(base + q + 1);
        u64 e2 = ((u64)f2u(f.z) << 32) | (u32)(base + q + 2);
        u64 e3 = ((u64)f2u(f.w) << 32) | (u32)(base + q + 3);
        cswap(e0, e1, true); cswap(e2, e3, false);            // k=2
        bool a4 = ((tid & 1) == 0);                           // k=4
        cswap(e0, e2, a4); cswap(e1, e3, a4);
        cswap(e0, e1, a4); cswap(e2, e3, a4);
        sh[q] = e0; sh[q + 1] = e1; sh[q + 2] = e2; sh[q + 3] = e3;
        __syncwarp();
    }

    for (int k = 8; k <= 128; k <<= 1)
        warp_gen(sh, seg, lane, k >> 1, k);
    __syncthreads();

    pair128_k256(sh, tid);                                    // k=256
    warp_finish64(sh, seg, lane, ((seg & 256) == 0));
    __syncthreads();
    fuse_256_128(sh, tid, ((tid >> 7) == 0));                 // k=512
    warp_finish64(sh, seg, lane, ((seg & 512) == 0));
    __syncthreads();
    {                                                         // k=1024
        bool A = ((rank & 1) == 0);
        fuse_512_256(sh, tid, A);
        pair128(sh, tid, A);
        warp_finish64(sh, seg, lane, A);
    }
    exchange(sh, shbase, rank ^ 1, ((rank ^ (rank >> 1)) & 1) == 0, tid);
    {                                                         // k=2048
        bool A = (((rank >> 1) & 1) == 0);
        fuse_512_256(sh, tid, A);
        pair128(sh, tid, A);
        warp_finish64(sh, seg, lane, A);
    }
    exchange(sh, shbase, rank ^ 2, (((rank >> 1) ^ (rank >> 2)) & 1) == 0, tid);
    exchange(sh, shbase, rank ^ 1, (((rank) ^ (rank >> 2)) & 1) == 0, tid);
    {                                                         // k=4096
        bool A = (((rank >> 2) & 1) == 0);
        fuse_512_256(sh, tid, A);
        pair128(sh, tid, A);
        warp_finish64(sh, seg, lane, A);
    }
    exchange(sh, shbase, rank ^ 4, (rank & 4) == 0, tid);     // k=8192
    exchange(sh, shbase, rank ^ 2, (rank & 2) == 0, tid);
    exchange(sh, shbase, rank ^ 1, (rank & 1) == 0, tid);
    fuse_512_256(sh, tid, true);
    pair128(sh, tid, true);
    warp_finish64(sh, seg, lane, true);

    u64* gk  = g_keys + row * NN + base;
    int* inv = g_inv  + row * NN;
    int eb = tid << 2;
#pragma unroll
    for (int m = 0; m < 4; m++) {
        u64 key = sh[eb + m];
        gk[eb + m] = key;
        inv[(u32)key & 8191u] = base + eb + m;
    }
}

// -------------------------------------------------------------------------
// Windows + perm generation: one warp per window; block covers
// (b, p0..p0+1) x all 4 h = one contiguous 32KB perm span.
// NEW: perm rows are built in a 32KB smem tile (STS.128) and streamed out
// with ONE cp.async.bulk per block -> store issue off the LSU path.
// -------------------------------------------------------------------------
__global__ void __launch_bounds__(256) windowsW(float* __restrict__ out) {
    __shared__ __align__(128) float tile[8192];   // 32KB: 8 warps x 4KB
    const unsigned FULL = 0xFFFFFFFFu;
    const float E_M8  = 3.3546262790251185e-4f;   // exp(-8)
    const float E_P56 = 2.0916595960130657e+24f;  // exp(56)
    int lane = threadIdx.x & 31;
    int wib  = threadIdx.x >> 5;                  // 0..7
    int b    = blockIdx.x >> 12;                  // 0..1
    int g    = blockIdx.x & 4095;                 // p-group
    int p    = (g << 1) | (wib >> 2);
    int h    = wib & 3;
    int row  = (b << 2) | h;
    int rb   = row * NN;

    int s   = g_inv[rb + p];
    int pos = (s + lane) & (NN - 1);
    u64 key = g_keys[rb + pos];
    int idx = (int)((u32)key & 8191u);
    u32 u   = (u32)(key >> 32);

    u32 prevu = __shfl_up_sync(FULL, u, 1);
    int eq = (lane > 0 && pos != 0 && u == prevu) ? 1 : 0;
    unsigned mask = __ballot_sync(FULL, eq);

    int t = lane;
    unsigned above = (t == 31) ? 0u : (mask >> (t + 1));
    int t1 = t + (__ffs(~above) - 1);                // tie-run end
    unsigned below = ~mask & (0xFFFFFFFFu >> (31 - t));
    int t0 = 31 - __clz(below);                      // tie-run start
    int m  = NN - s; if (m > 32) m = 32;             // wrap point
    int greater = (t < m) ? (m - 1 - t1) : (m + 31 - t1);
    int rank = greater + (t - t0);

    int pack = (idx << 6) | rank;                    // idx distinct -> stable
#pragma unroll
    for (int k2 = 2; k2 <= 32; k2 <<= 1) {
#pragma unroll
        for (int j = k2 >> 1; j > 0; j >>= 1) {
            int o = __shfl_xor_sync(FULL, pack, j);
            bool asc = ((lane & k2) == 0);
            bool low = ((lane & j) == 0);
            bool take = (asc == low) ? (o < pack) : (o > pack);
            if (take) pack = o;
        }
    }

    __stcs(out + (size_t)IDX_BASE + (size_t)(rb + p) * NK + lane,
           (float)(pack >> 6));
    int rk = pack & 63;

    float e = __expf(-2.0f * (float)lane);           // lane m holds exp(-2m)
    int c0 = (lane & 7) * 4;
    int arow = lane >> 3;

    int mm[4]; float v[4];
    {
        int r0 = __shfl_sync(FULL, rk, c0);
        int r1 = __shfl_sync(FULL, rk, c0 + 1);
        int r2 = __shfl_sync(FULL, rk, c0 + 2);
        int r3 = __shfl_sync(FULL, rk, c0 + 3);
        mm[0] = (arow - r0) & 31;  mm[1] = (arow - r1) & 31;
        mm[2] = (arow - r2) & 31;  mm[3] = (arow - r3) & 31;
        v[0] = __shfl_sync(FULL, e, mm[0]);
        v[1] = __shfl_sync(FULL, e, mm[1]);
        v[2] = __shfl_sync(FULL, e, mm[2]);
        v[3] = __shfl_sync(FULL, e, mm[3]);
    }

    float* tw = tile + (wib << 10);                  // warp's 4KB tile slice
    *reinterpret_cast<float4*>(tw + arow * 32 + c0) =
        make_float4(v[0], v[1], v[2], v[3]);
#pragma unroll
    for (int rnd = 1; rnd < 8; rnd++) {
#pragma unroll
        for (int c = 0; c < 4; c++) {
            mm[c] += 4;
            bool wrap = mm[c] >= 32;
            v[c] *= wrap ? E_P56 : E_M8;
            if (wrap) mm[c] -= 32;
        }
        int a = rnd * 4 + arow;
        *reinterpret_cast<float4*>(tw + a * 32 + c0) =
            make_float4(v[0], v[1], v[2], v[3]);
    }
    __syncthreads();

    // one 32KB bulk store: tile -> out at the block's contiguous span
    if (threadIdx.x == 0) {
        float* gdst = out + ((size_t)((b * NN + (g << 1)) * NH) << 10);
        u32 ssrc = smem_u32(tile);
        asm volatile("fence.proxy.async.shared::cta;" ::: "memory");
        asm volatile(
            "cp.async.bulk.global.shared::cta.bulk_group [%0], [%1], %2;"
            :: "l"(gdst), "r"(ssrc), "n"(32768) : "memory");
        asm volatile("cp.async.bulk.commit_group;" ::: "memory");
        asm volatile("cp.async.bulk.wait_group 0;" ::: "memory");
    }
}

extern "C" void kernel_launch(void* const* d_in, const int* in_sizes, int n_in,
                              void* d_out, int out_size) {
    const float* ranking = (const float*)d_in[0];   // (B,H,N,1) f32
    float* out = (float*)d_out;

    sortCluster8<<<64, 256>>>(ranking);
    windowsW<<<8192, 256>>>(out);
}

// round 15
// speedup vs baseline: 1.0424x; 1.0424x over previous
#include <cuda_runtime.h>
#include <stdint.h>

#define NB 2
#define NH 4
#define NN 8192
#define NK 32
#define NROWS 8
#define PERM_ELEMS (NB * NN * NH * NK * NK)   // 67,108,864
#define IDX_BASE   PERM_ELEMS

typedef unsigned long long u64;
typedef unsigned int u32;

// Scratch (device globals -> no allocation)
__device__ u64 g_keys[NROWS * NN];
__device__ int g_inv [NROWS * NN];

__device__ __forceinline__ u32 f2u(float f) {
    u32 b = __float_as_uint(f);
    return (b & 0x80000000u) ? ~b : (b | 0x80000000u);
}
__device__ __forceinline__ void cswap(u64& a, u64& b, bool asc) {
    if ((a > b) == asc) { u64 t = a; a = b; b = t; }
}
__device__ __forceinline__ void cluster_sync() {
    asm volatile("barrier.cluster.arrive.aligned;" ::: "memory");
    asm volatile("barrier.cluster.wait.aligned;" ::: "memory");
}
__device__ __forceinline__ u32 smem_u32(const void* p) {
    u32 a;
    asm("{ .reg .u64 t; cvta.to.shared.u64 t, %1; cvt.u32.u64 %0, t; }"
        : "=r"(a) : "l"(p));
    return a;
}
__device__ __forceinline__ u32 mapa_rank(u32 local, u32 rank) {
    u32 r;
    asm("mapa.shared::cluster.u32 %0, %1, %2;" : "=r"(r) : "r"(local), "r"(rank));
    return r;
}

// ---- warp-local pieces (validated; 128-elem segments) ----
__device__ __forceinline__ void warp_gen(u64* sh, int seg, int lane,
                                         int jhi, int k) {
    for (int j = jhi; j >= 4; j >>= 1) {
#pragma unroll
        for (int t = lane; t < 64; t += 32) {
            int i = ((t & ~(j - 1)) << 1) | (t & (j - 1));
            int p = i | j;
            bool asc = (((seg + i) & k) == 0);
            u64 a = sh[seg + i], b = sh[seg + p];
            if ((a > b) == asc) { sh[seg + i] = b; sh[seg + p] = a; }
        }
        __syncwarp();
    }
    int eb = seg + (lane << 2);
    bool asc = (((seg + (lane << 2)) & k) == 0);
    u64 e0 = sh[eb], e1 = sh[eb + 1], e2 = sh[eb + 2], e3 = sh[eb + 3];
    cswap(e0, e2, asc); cswap(e1, e3, asc);
    cswap(e0, e1, asc); cswap(e2, e3, asc);
    sh[eb] = e0; sh[eb + 1] = e1; sh[eb + 2] = e2; sh[eb + 3] = e3;
    __syncwarp();
}

__device__ __forceinline__ void warp_finish64(u64* sh, int seg, int lane,
                                              bool asc) {
    int b = seg + lane;
    {
        u64 e0 = sh[b], e1 = sh[b + 32], e2 = sh[b + 64], e3 = sh[b + 96];
        cswap(e0, e2, asc); cswap(e1, e3, asc);    // j=64
        cswap(e0, e1, asc); cswap(e2, e3, asc);    // j=32
        sh[b] = e0; sh[b + 32] = e1; sh[b + 64] = e2; sh[b + 96] = e3;
    }
    __syncwarp();
    for (int j = 16; j >= 4; j >>= 1) {
#pragma unroll
        for (int t = lane; t < 64; t += 32) {
            int i = ((t & ~(j - 1)) << 1) | (t & (j - 1));
            int p = i | j;
            u64 a = sh[seg + i], bb = sh[seg + p];
            if ((a > bb) == asc) { sh[seg + i] = bb; sh[seg + p] = a; }
        }
        __syncwarp();
    }
    int eb = seg + (lane << 2);
    u64 f0 = sh[eb], f1 = sh[eb + 1], f2 = sh[eb + 2], f3 = sh[eb + 3];
    cswap(f0, f2, asc); cswap(f1, f3, asc);
    cswap(f0, f1, asc); cswap(f2, f3, asc);
    sh[eb] = f0; sh[eb + 1] = f1; sh[eb + 2] = f2; sh[eb + 3] = f3;
    __syncwarp();
}

// ---- chunk=1024 register-fused block phases (256 threads) ----
__device__ __forceinline__ void fuse_512_256(u64* sh, int tid, bool asc) {
    u64 e0 = sh[tid], e1 = sh[tid + 256], e2 = sh[tid + 512], e3 = sh[tid + 768];
    cswap(e0, e2, asc); cswap(e1, e3, asc);    // j=512
    cswap(e0, e1, asc); cswap(e2, e3, asc);    // j=256
    sh[tid] = e0; sh[tid + 256] = e1; sh[tid + 512] = e2; sh[tid + 768] = e3;
    __syncthreads();
}
__device__ __forceinline__ void fuse_256_128(u64* sh, int tid, bool asc) {
    int b = ((tid >> 7) << 9) | (tid & 127);
    u64 e0 = sh[b], e1 = sh[b + 128], e2 = sh[b + 256], e3 = sh[b + 384];
    cswap(e0, e2, asc); cswap(e1, e3, asc);    // j=256
    cswap(e0, e1, asc); cswap(e2, e3, asc);    // j=128
    sh[b] = e0; sh[b + 128] = e1; sh[b + 256] = e2; sh[b + 384] = e3;
    __syncthreads();
}
__device__ __forceinline__ void pair128(u64* sh, int tid, bool asc) {
    int b = ((tid >> 7) << 9) | (tid & 127);
    u64 e0 = sh[b], e1 = sh[b + 128], e2 = sh[b + 256], e3 = sh[b + 384];
    cswap(e0, e1, asc); cswap(e2, e3, asc);
    sh[b] = e0; sh[b + 128] = e1; sh[b + 256] = e2; sh[b + 384] = e3;
    __syncthreads();
}
__device__ __forceinline__ void pair128_k256(u64* sh, int tid) {
    int b = ((tid >> 7) << 9) | (tid & 127);
    u64 e0 = sh[b], e1 = sh[b + 128], e2 = sh[b + 256], e3 = sh[b + 384];
    cswap(e0, e1, true); cswap(e2, e3, false);
    sh[b] = e0; sh[b + 128] = e1; sh[b + 256] = e2; sh[b + 384] = e3;
    __syncthreads();
}

// Double-buffered cross-CTA exchange: ONE cluster_sync (entry). Reads peer's
// src, writes own dst. The NEXT exchange's entry sync guarantees all peers
// finished reading src before it is overwritten. barrier.cluster orders the
// preceding smem writes for peer visibility. Keys unique -> consistent picks.
__device__ __forceinline__ void exchange_db(const u64* src, u64* dst,
                                            u32 src_sm, int partner,
                                            bool keep_min, int tid) {
    cluster_sync();                         // peers' src finalized
    u64 peer[4];
    u32 remote = mapa_rank(src_sm, (u32)partner);
#pragma unroll
    for (int m = 0; m < 4; m++) {
        u32 addr = remote + (u32)((tid + (m << 8)) << 3);
        asm volatile("ld.shared::cluster.b64 %0, [%1];" : "=l"(peer[m]) : "r"(addr));
    }
#pragma unroll
    for (int m = 0; m < 4; m++) {
        int l = tid + (m << 8);
        u64 mine = src[l];
        bool take = keep_min ? (peer[m] < mine) : (peer[m] > mine);
        dst[l] = take ? peer[m] : mine;
    }
    __syncthreads();                        // dst complete for block phases
}

// -------------------------------------------------------------------------
// Full stable argsort of 8 rows x 8192, ONE launch, 64 CTAs.
// 8 clusters x 8 CTAs, 1024-elem chunk per CTA, 256 threads.
// Double-buffered DSMEM exchanges: 6 cluster_syncs total (was 12).
// Buffers: A for k<=1024 local; then A->B (k2048), B->A,A->B (k4096),
// B->A,A->B,B->A (k8192); extract from A.
// -------------------------------------------------------------------------
__global__ void __launch_bounds__(256) __cluster_dims__(8, 1, 1)
sortCluster8(const float* __restrict__ r) {
    __shared__ u64 bufA[1024];
    __shared__ u64 bufB[1024];
    int tid  = threadIdx.x, lane = tid & 31, warp = tid >> 5;
    int row  = blockIdx.x >> 3;
    int rank = blockIdx.x & 7;
    int base = rank << 10;
    const float* rr = r + row * NN;
    u32 smA = smem_u32(bufA), smB = smem_u32(bufB);
    int seg = warp << 7;

    {
        int q = tid << 2;
        float4 f = *reinterpret_cast<const float4*>(rr + base + q);
        u64 e0 = ((u64)f2u(f.x) << 32) | (u32)(base + q);
        u64 e1 = ((u64)f2u(f.y) << 32) | (u32)(base + q + 1);
        u64 e2 = ((u64)f2u(f.z) << 32) | (u32)(base + q + 2);
        u64 e3 = ((u64)f2u(f.w) << 32) | (u32)(base + q + 3);
        cswap(e0, e1, true); cswap(e2, e3, false);            // k=2
        bool a4 = ((tid & 1) == 0);                           // k=4
        cswap(e0, e2, a4); cswap(e1, e3, a4);
        cswap(e0, e1, a4); cswap(e2, e3, a4);
        bufA[q] = e0; bufA[q + 1] = e1; bufA[q + 2] = e2; bufA[q + 3] = e3;
        __syncwarp();
    }

    for (int k = 8; k <= 128; k <<= 1)
        warp_gen(bufA, seg, lane, k >> 1, k);
    __syncthreads();

    pair128_k256(bufA, tid);                                  // k=256
    warp_finish64(bufA, seg, lane, ((seg & 256) == 0));
    __syncthreads();
    fuse_256_128(bufA, tid, ((tid >> 7) == 0));               // k=512
    warp_finish64(bufA, seg, lane, ((seg & 512) == 0));
    __syncthreads();
    {                                                         // k=1024
        bool A = ((rank & 1) == 0);
        fuse_512_256(bufA, tid, A);
        pair128(bufA, tid, A);
        warp_finish64(bufA, seg, lane, A);
        __syncthreads();
    }
    // ---- k=2048: cross j=1024 (A->B), local on B ----
    exchange_db(bufA, bufB, smA, rank ^ 1,
                ((rank ^ (rank >> 1)) & 1) == 0, tid);
    {
        bool A = (((rank >> 1) & 1) == 0);
        fuse_512_256(bufB, tid, A);
        pair128(bufB, tid, A);
        warp_finish64(bufB, seg, lane, A);
        __syncthreads();
    }
    // ---- k=4096: cross j=2048 (B->A), j=1024 (A->B), local on B ----
    exchange_db(bufB, bufA, smB, rank ^ 2,
                (((rank >> 1) ^ (rank >> 2)) & 1) == 0, tid);
    exchange_db(bufA, bufB, smA, rank ^ 1,
                (((rank) ^ (rank >> 2)) & 1) == 0, tid);
    {
        bool A = (((rank >> 2) & 1) == 0);
        fuse_512_256(bufB, tid, A);
        pair128(bufB, tid, A);
        warp_finish64(bufB, seg, lane, A);
        __syncthreads();
    }
    // ---- k=8192 (asc): cross j=4096 (B->A), j=2048 (A->B), j=1024 (B->A) ----
    exchange_db(bufB, bufA, smB, rank ^ 4, (rank & 4) == 0, tid);
    exchange_db(bufA, bufB, smA, rank ^ 2, (rank & 2) == 0, tid);
    exchange_db(bufB, bufA, smB, rank ^ 1, (rank & 1) == 0, tid);
    fuse_512_256(bufA, tid, true);
    pair128(bufA, tid, true);
    warp_finish64(bufA, seg, lane, true);

    // ---- extract (quad-local: slots this thread just wrote) ----
    u64* gk  = g_keys + row * NN + base;
    int* inv = g_inv  + row * NN;
    int eb = tid << 2;
#pragma unroll
    for (int m = 0; m < 4; m++) {
        u64 key = bufA[eb + m];
        gk[eb + m] = key;
        inv[(u32)key & 8191u] = base + eb + m;
    }
}

// -------------------------------------------------------------------------
// Windows + perm generation (R13-validated, 40.3us): one warp per window;
// block covers (b, p0..p0+1) x all 4 h -> contiguous 32KB output span.
// -------------------------------------------------------------------------
__global__ void __launch_bounds__(256) windowsW(float* __restrict__ out) {
    const unsigned FULL = 0xFFFFFFFFu;
    const float E_M8  = 3.3546262790251185e-4f;   // exp(-8)
    const float E_P56 = 2.0916595960130657e+24f;  // exp(56)
    int lane = threadIdx.x & 31;
    int wib  = threadIdx.x >> 5;                  // 0..7
    int b    = blockIdx.x >> 12;                  // 0..1
    int g    = blockIdx.x & 4095;                 // p-group
    int p    = (g << 1) | (wib >> 2);
    int h    = wib & 3;
    int row  = (b << 2) | h;
    int rb   = row * NN;

    int s   = g_inv[rb + p];
    int pos = (s + lane) & (NN - 1);
    u64 key = g_keys[rb + pos];
    int idx = (int)((u32)key & 8191u);
    u32 u   = (u32)(key >> 32);

    u32 prevu = __shfl_up_sync(FULL, u, 1);
    int eq = (lane > 0 && pos != 0 && u == prevu) ? 1 : 0;
    unsigned mask = __ballot_sync(FULL, eq);

    int t = lane;
    unsigned above = (t == 31) ? 0u : (mask >> (t + 1));
    int t1 = t + (__ffs(~above) - 1);                // tie-run end
    unsigned below = ~mask & (0xFFFFFFFFu >> (31 - t));
    int t0 = 31 - __clz(below);                      // tie-run start
    int m  = NN - s; if (m > 32) m = 32;             // wrap point
    int greater = (t < m) ? (m - 1 - t1) : (m + 31 - t1);
    int rank = greater + (t - t0);

    int pack = (idx << 6) | rank;                    // idx distinct -> stable
#pragma unroll
    for (int k2 = 2; k2 <= 32; k2 <<= 1) {
#pragma unroll
        for (int j = k2 >> 1; j > 0; j >>= 1) {
            int o = __shfl_xor_sync(FULL, pack, j);
            bool asc = ((lane & k2) == 0);
            bool low = ((lane & j) == 0);
            bool take = (asc == low) ? (o < pack) : (o > pack);
            if (take) pack = o;
        }
    }

    __stcs(out + (size_t)IDX_BASE + (size_t)(rb + p) * NK + lane,
           (float)(pack >> 6));
    int rk = pack & 63;

    float e = __expf(-2.0f * (float)lane);           // lane m holds exp(-2m)
    int c0 = (lane & 7) * 4;
    int arow = lane >> 3;

    int mm[4]; float v[4];
    {
        int r0 = __shfl_sync(FULL, rk, c0);
        int r1 = __shfl_sync(FULL, rk, c0 + 1);
        int r2 = __shfl_sync(FULL, rk, c0 + 2);
        int r3 = __shfl_sync(FULL, rk, c0 + 3);
        mm[0] = (arow - r0) & 31;  mm[1] = (arow - r1) & 31;
        mm[2] = (arow - r2) & 31;  mm[3] = (arow - r3) & 31;
        v[0] = __shfl_sync(FULL, e, mm[0]);
        v[1] = __shfl_sync(FULL, e, mm[1]);
        v[2] = __shfl_sync(FULL, e, mm[2]);
        v[3] = __shfl_sync(FULL, e, mm[3]);
    }

    float* po = out + ((size_t)((b * NN + p) * NH + h) << 10);  // (B,N,H,K,K)

    __stcs(reinterpret_cast<float4*>(po + arow * 32 + c0),
           make_float4(v[0], v[1], v[2], v[3]));
#pragma unroll
    for (int rnd = 1; rnd < 8; rnd++) {
#pragma unroll
        for (int c = 0; c < 4; c++) {
            mm[c] += 4;
            bool wrap = mm[c] >= 32;
            v[c] *= wrap ? E_P56 : E_M8;
            if (wrap) mm[c] -= 32;
        }
        int a = rnd * 4 + arow;
        __stcs(reinterpret_cast<float4*>(po + a * 32 + c0),
               make_float4(v[0], v[1], v[2], v[3]));
    }
}

extern "C" void kernel_launch(void* const* d_in, const int* in_sizes, int n_in,
                              void* d_out, int out_size) {
    const float* ranking = (const float*)d_in[0];   // (B,H,N,1) f32
    float* out = (float*)d_out;

    sortCluster8<<<64, 256>>>(ranking);
    windowsW<<<8192, 256>>>(out);
}